// round 15
// baseline (speedup 1.0000x reference)
#include <cuda_runtime.h>

#define HALF     512
#define BATCH    8192
#define DEPTH    20
#define TB       16          // batch columns per block (4 bq threads x 4 cols)
#define NTHREADS 128         // 32 row-threads x 4 batch-quad threads
#define NBLOCKS  (BATCH / TB)

// Scalar (c, s) coefficients, 8B each. P1-type layers (l%10 < 5) stored
// PERMUTED: natural pair p -> slot (p&15)*32 + (p>>4), so BOTH pass types
// address coefs as m*32 + rt; a warp's 8 consecutive rt values read 64
// consecutive bytes, broadcast across the 4 bq lanes.
__device__ float2 g_cs[DEPTH * HALF];

__global__ void sincos_kernel(const float* __restrict__ ang) {
    int i = blockIdx.x * blockDim.x + threadIdx.x;
    if (i < DEPTH * HALF) {
        const int l = i / HALF;
        const int p = i % HALF;
        float s, c;
        sincosf(ang[i], &s, &c);
        const int slot = ((l % 10) < 5) ? ((p & 15) * 32 + (p >> 4)) : p;
        g_cs[l * HALF + slot] = make_float2(c, s);
    }
}

// Scalar Givens rotation on one column: y0 = c*x0 + s*x1 ; y1 = c*x1 - s*x0.
// The negation folds into the FFMA addend operand (free in SASS).
__device__ __forceinline__ void rots(float& x0, float& x1, float c, float s) {
    const float t0 = s * x1;
    const float t1 = s * x0;
    x0 = fmaf(c, x0, t0);
    x1 = fmaf(c, x1, -t1);
}

// Five butterfly levels fully in registers on 4 independent scalar column
// arrays (64 independent FFMA/FMUL per q-step, no broadcasts, no ALU ops).
// Flattened into 20 q-steps with a dist-1 pipelined coefficient stream.
// Coef slot = m*32 + rt; pairs (j, j+2^l), j = ((m>>l)<<(l+1)) | (m & (2^l-1)).
__device__ __forceinline__ void pass5(float* X0, float* X1, float* X2, float* X3,
                                      const float2* __restrict__ lt) {
    float2 cf[4];
#pragma unroll
    for (int t = 0; t < 4; ++t) cf[t] = __ldg(lt + t * 32);

#pragma unroll
    for (int u = 0; u < 20; ++u) {
        const int l = u >> 2;
        const int q = u & 3;
        float2 nf[4];
        if (u < 19) {
            const int l2 = (u + 1) >> 2;
            const int q2 = (u + 1) & 3;
#pragma unroll
            for (int t = 0; t < 4; ++t)
                nf[t] = __ldg(lt + l2 * HALF + (q2 * 4 + t) * 32);
        }
#pragma unroll
        for (int t = 0; t < 4; ++t) {
            const int m  = q * 4 + t;
            const int sg = 1 << l;
            const int j  = ((m >> l) << (l + 1)) | (m & (sg - 1));
            const float c = cf[t].x, s = cf[t].y;
            rots(X0[j], X0[j + sg], c, s);
            rots(X1[j], X1[j + sg], c, s);
            rots(X2[j], X2[j + sg], c, s);
            rots(X3[j], X3[j + sg], c, s);
        }
#pragma unroll
        for (int t = 0; t < 4; ++t) cf[t] = nf[t];
    }
}

// Smem swizzle in 16B units (hardware-verified in R5/R10):
// addr(row,bq) = ((row ^ ((row>>5)&1)) << 2) | bq. For warp = 8 rt x 4 bq,
// both exchange groupings hit each 128B bank-group with exactly 4 lanes ->
// 512B warp accesses at the 4-phase minimum. Bijective.
#define ADRA(j) (baseA + (((j) ^ eA) << 2))                 // row = rt*32+j
#define ADRB(j) ((j) * 128 + (((j) & 1) ? baseB1 : baseB0)) // row = rt+32j

extern "C" __global__ void __launch_bounds__(NTHREADS, 2)
butterfly_kernel(const float* __restrict__ X, float* __restrict__ Y)
{
    extern __shared__ float4 tile[];       // 1024 rows x 4 bq x 16B = 64 KB

    const int bq = threadIdx.x & 3;        // batch-quad (4 cols) 0..3
    const int rt = threadIdx.x >> 2;       // row-thread 0..31
    const long long bb = (long long)blockIdx.x * TB + bq * 4;

    const int eA     = rt & 1;
    const int baseA  = rt * 128 + bq;
    const int baseB0 = (rt << 2) + bq;
    const int baseB1 = ((rt ^ 1) << 2) + bq;

    float X0[32], X1[32], X2[32], X3[32];  // 32 rows x 4 scalar batch columns

    // Load, layout A (reg j = row rt*32+j); .cg keeps L1 for the coef table.
#pragma unroll
    for (int j = 0; j < 32; ++j) {
        const float4 v = __ldcg(
            reinterpret_cast<const float4*>(X + (long long)(rt * 32 + j) * BATCH + bb));
        X0[j] = v.x; X1[j] = v.y; X2[j] = v.z; X3[j] = v.w;
    }

    const float2* lt = g_cs + rt;

#pragma unroll 1
    for (int sp = 0; sp < 2; ++sp) {
        // layers sp*10 .. sp*10+4 (register strides 1..16 in layout A)
        pass5(X0, X1, X2, X3, lt + (sp * 10) * HALF);

        // exchange A -> B
        __syncthreads();
#pragma unroll
        for (int j = 0; j < 32; ++j)
            tile[ADRA(j)] = make_float4(X0[j], X1[j], X2[j], X3[j]);
        __syncthreads();
#pragma unroll
        for (int j = 0; j < 32; ++j) {
            const float4 v = tile[ADRB(j)];
            X0[j] = v.x; X1[j] = v.y; X2[j] = v.z; X3[j] = v.w;
        }

        // layers sp*10+5 .. sp*10+9 (strides 32..512 in layout B)
        pass5(X0, X1, X2, X3, lt + (sp * 10 + 5) * HALF);

        if (sp == 0) {
            // exchange B -> A
            __syncthreads();
#pragma unroll
            for (int j = 0; j < 32; ++j)
                tile[ADRB(j)] = make_float4(X0[j], X1[j], X2[j], X3[j]);
            __syncthreads();
#pragma unroll
            for (int j = 0; j < 32; ++j) {
                const float4 v = tile[ADRA(j)];
                X0[j] = v.x; X1[j] = v.y; X2[j] = v.z; X3[j] = v.w;
            }
        }
    }

    // Store, layout B (reg j = row rt+32j), .cg to bypass L1.
#pragma unroll
    for (int j = 0; j < 32; ++j)
        __stcg(reinterpret_cast<float4*>(Y + (long long)(rt + 32 * j) * BATCH + bb),
               make_float4(X0[j], X1[j], X2[j], X3[j]));
}

extern "C" void kernel_launch(void* const* d_in, const int* in_sizes, int n_in,
                              void* d_out, int out_size)
{
    const float* X = (const float*)d_in[0];
    const float* A = (const float*)d_in[1];
    if (n_in >= 2 && in_sizes[0] < in_sizes[1]) {   // defensive: X is the big one
        const float* t = X; X = A; A = t;
    }
    float* Y = (float*)d_out;

    cudaFuncSetAttribute(butterfly_kernel,
                         cudaFuncAttributeMaxDynamicSharedMemorySize, 65536);

    sincos_kernel<<<(DEPTH * HALF + 255) / 256, 256>>>(A);
    butterfly_kernel<<<NBLOCKS, NTHREADS, 65536>>>(X, Y);
}

// round 16
// speedup vs baseline: 1.0512x; 1.0512x over previous
#include <cuda_runtime.h>

typedef unsigned long long u64;

#define HALF     512
#define BATCH    8192
#define DEPTH    20
#define TB       16          // batch columns per block (4 bq threads x 4 cols)
#define NTHREADS 128         // 32 row-threads x 4 batch-quad threads
#define NBLOCKS  (BATCH / TB)

// Scalar (c, s) coefficients, 8B each. P1-type layers (l%10 < 5) stored
// PERMUTED: natural pair p -> slot (p&15)*32 + (p>>4), so BOTH pass types
// address coefs as m*32 + rt; a warp's 8 consecutive rt values read 64
// consecutive bytes, broadcast across the 4 bq lanes.
__device__ float2 g_cs[DEPTH * HALF];

__global__ void sincos_kernel(const float* __restrict__ ang) {
    int i = blockIdx.x * blockDim.x + threadIdx.x;
    if (i < DEPTH * HALF) {
        const int l = i / HALF;
        const int p = i % HALF;
        float s, c;
        sincosf(ang[i], &s, &c);
        const int slot = ((l % 10) < 5) ? ((p & 15) * 32 + (p >> 4)) : p;
        g_cs[l * HALF + slot] = make_float2(c, s);
    }
}

// ---- packed f32x2 helpers (sm_100) ----
__device__ __forceinline__ u64 pk2(float v) {
    u64 r; asm("mov.b64 %0, {%1, %1};" : "=l"(r) : "f"(v)); return r;
}
__device__ __forceinline__ u64 mul2(u64 a, u64 b) {
    u64 d; asm("mul.rn.f32x2 %0, %1, %2;" : "=l"(d) : "l"(a), "l"(b)); return d;
}
__device__ __forceinline__ u64 fma2(u64 a, u64 b, u64 c) {
    u64 d; asm("fma.rn.f32x2 %0, %1, %2, %3;" : "=l"(d) : "l"(a), "l"(b), "l"(c)); return d;
}

// Givens rotation on one packed pair: y0 = c*x0 + s*x1 ; y1 = -s*x0 + c*x1
__device__ __forceinline__ void rot(u64& x0, u64& x1, u64 cc, u64 ss, u64 ns) {
    const u64 y0 = fma2(cc, x0, mul2(ss, x1));
    const u64 y1 = fma2(ns, x0, mul2(cc, x1));
    x0 = y0; x1 = y1;
}

// Five butterfly levels fully in registers on 4 batch columns (Xa, Xb -> 4
// independent FMA chains per rotation). Flattened into 20 q-steps with a
// dist-1 pipelined coefficient stream.
// Coef slot = m*32 + rt; pairs (j, j+2^l), j = ((m>>l)<<(l+1)) | (m & (2^l-1)).
__device__ __forceinline__ void pass5(u64* Xa, u64* Xb, const float2* __restrict__ lt) {
    float2 cf[4];
#pragma unroll
    for (int t = 0; t < 4; ++t) cf[t] = __ldg(lt + t * 32);

#pragma unroll
    for (int u = 0; u < 20; ++u) {
        const int l = u >> 2;
        const int q = u & 3;
        float2 nf[4];
        if (u < 19) {
            const int l2 = (u + 1) >> 2;
            const int q2 = (u + 1) & 3;
#pragma unroll
            for (int t = 0; t < 4; ++t)
                nf[t] = __ldg(lt + l2 * HALF + (q2 * 4 + t) * 32);
        }
#pragma unroll
        for (int t = 0; t < 4; ++t) {
            const int m  = q * 4 + t;
            const int sg = 1 << l;
            const int j  = ((m >> l) << (l + 1)) | (m & (sg - 1));
            const u64 cc = pk2(cf[t].x);
            const u64 ss = pk2(cf[t].y);
            const u64 ns = ss ^ 0x8000000080000000ULL;
            rot(Xa[j], Xa[j + sg], cc, ss, ns);
            rot(Xb[j], Xb[j + sg], cc, ss, ns);
        }
#pragma unroll
        for (int t = 0; t < 4; ++t) cf[t] = nf[t];
    }
}

// Smem swizzle in 16B units (hardware-verified in R5/R10):
// addr(row,bq) = ((row ^ ((row>>5)&1)) << 2) | bq. For warp = 8 rt x 4 bq,
// both exchange groupings hit each 128B bank-group with exactly 4 lanes ->
// 512B warp accesses at the 4-phase minimum. Bijective.
#define ADRA(j) (baseA + (((j) ^ eA) << 2))                 // row = rt*32+j
#define ADRB(j) ((j) * 128 + (((j) & 1) ? baseB1 : baseB0)) // row = rt+32j

extern "C" __global__ void __launch_bounds__(NTHREADS, 2)
butterfly_kernel(const float* __restrict__ X, float* __restrict__ Y)
{
    extern __shared__ ulonglong2 tile[];   // 1024 rows x 4 bq x 16B = 64 KB

    const int bq = threadIdx.x & 3;        // batch-quad (4 cols) 0..3
    const int rt = threadIdx.x >> 2;       // row-thread 0..31
    const long long bb = (long long)blockIdx.x * TB + bq * 4;

    const int eA     = rt & 1;
    const int baseA  = rt * 128 + bq;
    const int baseB0 = (rt << 2) + bq;
    const int baseB1 = ((rt ^ 1) << 2) + bq;

    u64 Xa[32], Xb[32];                    // 32 rows x 4 batch columns

    // Load, layout A (reg j = row rt*32+j); .cg keeps L1 for the coef table.
#pragma unroll
    for (int j = 0; j < 32; ++j) {
        const float4 v = __ldcg(
            reinterpret_cast<const float4*>(X + (long long)(rt * 32 + j) * BATCH + bb));
        asm("mov.b64 %0, {%2, %3}; mov.b64 %1, {%4, %5};"
            : "=l"(Xa[j]), "=l"(Xb[j]) : "f"(v.x), "f"(v.y), "f"(v.z), "f"(v.w));
    }

    // Single phase loop: pass5 is instantiated ONCE -> SASS body ~25KB (fits
    // L1.5 I$, reused 4x) instead of ~72KB straight-line (streams from L2 I$).
    // ph 0,2: layout A (strides 1..16); ph 1,3: layout B (strides 32..512).
#pragma unroll 1
    for (int ph = 0; ph < 4; ++ph) {
        pass5(Xa, Xb, g_cs + rt + (ph * 5) * HALF);

        if (ph < 3) {
            __syncthreads();
            if ((ph & 1) == 0) {           // exchange A -> B
#pragma unroll
                for (int j = 0; j < 32; ++j) tile[ADRA(j)] = make_ulonglong2(Xa[j], Xb[j]);
                __syncthreads();
#pragma unroll
                for (int j = 0; j < 32; ++j) {
                    const ulonglong2 v = tile[ADRB(j)];
                    Xa[j] = v.x; Xb[j] = v.y;
                }
            } else {                       // exchange B -> A
#pragma unroll
                for (int j = 0; j < 32; ++j) tile[ADRB(j)] = make_ulonglong2(Xa[j], Xb[j]);
                __syncthreads();
#pragma unroll
                for (int j = 0; j < 32; ++j) {
                    const ulonglong2 v = tile[ADRA(j)];
                    Xa[j] = v.x; Xb[j] = v.y;
                }
            }
        }
    }

    // Store, layout B (reg j = row rt+32j), .cg to bypass L1.
#pragma unroll
    for (int j = 0; j < 32; ++j) {
        float x, y, z, w;
        asm("mov.b64 {%0, %1}, %4; mov.b64 {%2, %3}, %5;"
            : "=f"(x), "=f"(y), "=f"(z), "=f"(w) : "l"(Xa[j]), "l"(Xb[j]));
        __stcg(reinterpret_cast<float4*>(Y + (long long)(rt + 32 * j) * BATCH + bb),
               make_float4(x, y, z, w));
    }
}

extern "C" void kernel_launch(void* const* d_in, const int* in_sizes, int n_in,
                              void* d_out, int out_size)
{
    const float* X = (const float*)d_in[0];
    const float* A = (const float*)d_in[1];
    if (n_in >= 2 && in_sizes[0] < in_sizes[1]) {   // defensive: X is the big one
        const float* t = X; X = A; A = t;
    }
    float* Y = (float*)d_out;

    cudaFuncSetAttribute(butterfly_kernel,
                         cudaFuncAttributeMaxDynamicSharedMemorySize, 65536);

    sincos_kernel<<<(DEPTH * HALF + 255) / 256, 256>>>(A);
    butterfly_kernel<<<NBLOCKS, NTHREADS, 65536>>>(X, Y);
}